// round 6
// baseline (speedup 1.0000x reference)
#include <cuda_runtime.h>
#include <cuda_bf16.h>
#include <cstdint>

#define BATCH 8
#define SEQ   8192
#define BS    65536
#define MC    48
#define OF    88
#define NG    8
#define HD    6
#define KW    31
#define PADW  15
#define N144  144

// ---------------- device scratch ----------------
__device__ float g_qkv1[(size_t)BS * N144];
__device__ float g_x2  [(size_t)BS * 136];
__device__ float g_qkv2[(size_t)BS * N144];

// ---------------- fused QKV projection GEMM ----------------
// C[M,144] = X[M,K]*[Wq;Wk;Wv]^T. Block 128x144, 192 thr, 8x12 thread tile,
// K-step 12, register prefetch, vectorized B loads.
template <int K>
__global__ __launch_bounds__(192, 2) void gemm_qkv(
    const float* __restrict__ x,
    const float* __restrict__ Wq, const float* __restrict__ Wk,
    const float* __restrict__ Wv,
    float* __restrict__ out)
{
    __shared__ __align__(16) float xs[128 * 13];   // [m][kk], pitch 13
    __shared__ __align__(16) float ws[12 * 148];   // [kk][n], pitch 148

    const int tid = threadIdx.x;
    const int ty = tid / 12;          // 0..15 -> rows ty*8..+7
    const int tx = tid % 12;          // 0..11 -> cols seg*48 + tx*4
    const int row0 = blockIdx.x * 128;

    float acc[8][12];
#pragma unroll
    for (int r = 0; r < 8; r++)
#pragma unroll
        for (int c = 0; c < 12; c++) acc[r][c] = 0.f;

    float rx[8], rw[9];

    auto loadX = [&](int k0) {
#pragma unroll
        for (int j = 0; j < 8; j++) {
            int i = tid + j * 192;         // < 1536
            int m = i / 12, kk = i % 12;
            int col = k0 + kk;
            rx[j] = (col < K) ? x[(size_t)(row0 + m) * K + col] : 0.f;
        }
    };
    auto loadW = [&](int k0) {
#pragma unroll
        for (int j = 0; j < 9; j++) {
            int i = tid + j * 192;         // < 1728
            int n = i / 12, kk = i % 12;
            int col = k0 + kk;
            float w = 0.f;
            if (col < K) {
                const float* Wp; int nr;
                if (n < 48)      { Wp = Wq; nr = n; }
                else if (n < 96) { Wp = Wk; nr = n - 48; }
                else             { Wp = Wv; nr = n - 96; }
                w = Wp[nr * K + col];
            }
            rw[j] = w;
        }
    };

    loadX(0); loadW(0);

    const int NSTEP = (K + 11) / 12;
    for (int s = 0; s < NSTEP; s++) {
        // commit staged registers to smem
#pragma unroll
        for (int j = 0; j < 8; j++) {
            int i = tid + j * 192;
            int m = i / 12, kk = i % 12;
            xs[m * 13 + kk] = rx[j];
        }
#pragma unroll
        for (int j = 0; j < 9; j++) {
            int i = tid + j * 192;
            int n = i / 12, kk = i % 12;
            ws[kk * 148 + n] = rw[j];
        }
        __syncthreads();

        if (s + 1 < NSTEP) { loadX((s + 1) * 12); loadW((s + 1) * 12); }

#pragma unroll
        for (int kk = 0; kk < 12; kk++) {
            float a[8];
#pragma unroll
            for (int r = 0; r < 8; r++) a[r] = xs[(ty * 8 + r) * 13 + kk];
            float4 b0 = *reinterpret_cast<const float4*>(&ws[kk * 148 +   0 + tx * 4]);
            float4 b1 = *reinterpret_cast<const float4*>(&ws[kk * 148 +  48 + tx * 4]);
            float4 b2 = *reinterpret_cast<const float4*>(&ws[kk * 148 +  96 + tx * 4]);
            float bv[12] = {b0.x, b0.y, b0.z, b0.w, b1.x, b1.y, b1.z, b1.w,
                            b2.x, b2.y, b2.z, b2.w};
#pragma unroll
            for (int r = 0; r < 8; r++)
#pragma unroll
                for (int c = 0; c < 12; c++)
                    acc[r][c] = fmaf(a[r], bv[c], acc[r][c]);
        }
        __syncthreads();
    }
#pragma unroll
    for (int r = 0; r < 8; r++) {
        size_t base = (size_t)(row0 + ty * 8 + r) * N144;
#pragma unroll
        for (int seg = 0; seg < 3; seg++) {
            float4 v = make_float4(acc[r][seg * 4], acc[r][seg * 4 + 1],
                                   acc[r][seg * 4 + 2], acc[r][seg * 4 + 3]);
            *reinterpret_cast<float4*>(&out[base + seg * 48 + tx * 4]) = v;
        }
    }
}

// ---------------- attention + LN + sigmoid-proj ----------------
// Block: 32 rows, 256 threads. Thread = (row, group).
// A/B split layout, 128-float (512B) row pitch so every LDS.128 phase is one
// aligned 128B wavefront. Per kv row: A_k[32]|B_k[32]|A_v[32]|B_v[32];
// channel c (g=c/6,d=c%6) at quad base + g*4 + d (d<4) or B-quad g*4+(d-4),
// B slots +2,+3 zero.
constexpr int RPB  = 32;
constexpr int HALO = RPB + 2 * PADW;      // 62
constexpr int KV8P = 128;                  // 512B pitch (aligned)
constexpr int RELP8 = 64;                  // 256B pitch (aligned)
constexpr int XSP  = 49;

constexpr int OFF_KV  = 0;                          // [62][128] = 7936
constexpr int OFF_REL = OFF_KV + HALO * KV8P;       // [31][64]  (128B aligned)
constexpr int OFF_WOT = OFF_REL + KW * RELP8;       // [48][88]
constexpr int OFF_XS  = OFF_WOT + MC * OF;          // [32][49]
constexpr int OFF_BO  = OFF_XS + RPB * XSP;
constexpr int OFF_LNG = OFF_BO + OF;
constexpr int OFF_LNB = OFF_LNG + MC;
constexpr int SMEM_F  = OFF_LNB + MC;
constexpr int SMEM_BYTES = SMEM_F * 4;              // ~63.6 KB -> 3 CTAs/SM

__device__ __forceinline__ float dot8(const float* q, float4 a, float4 b) {
    float e = q[0] * a.x;
    e = fmaf(q[1], a.y, e); e = fmaf(q[2], a.z, e); e = fmaf(q[3], a.w, e);
    e = fmaf(q[4], b.x, e); e = fmaf(q[5], b.y, e); e = fmaf(q[6], b.z, e);
    e = fmaf(q[7], b.w, e);
    return e;
}

template <bool FIRST>
__global__ __launch_bounds__(256, 3) void attn_block(
    const float* __restrict__ rel,
    const float* __restrict__ lng, const float* __restrict__ lnb,
    const float* __restrict__ Wp,      // [88,48]
    const float* __restrict__ bp,
    float* __restrict__ pred_out,      // [BS,88]
    float* __restrict__ a_out)         // [BS,248] (FIRST only)
{
    extern __shared__ __align__(16) float sm[];
    float* kv8  = sm + OFF_KV;
    float* relT = sm + OFF_REL;
    float* WoT  = sm + OFF_WOT;
    float* xs   = sm + OFF_XS;
    float* boS  = sm + OFF_BO;
    float* lngS = sm + OFF_LNG;
    float* lnbS = sm + OFF_LNB;

    const float* qkv = FIRST ? g_qkv1 : g_qkv2;

    const int tid = threadIdx.x;
    const int row0 = blockIdx.x * RPB;
    const int bi = row0 / SEQ;
    const int lo = bi * SEQ, hi = lo + SEQ;

    // ---- stage k/v: full 62x128 region in one pass (data + pads) ----
    for (int i = tid; i < HALO * KV8P; i += 256) {
        int hr = i >> 7, col = i & 127;
        int quad = col >> 5;            // 0:A_k 1:B_k 2:A_v 3:B_v
        int w = col & 31;
        int g = w >> 2, dd = w & 3;
        int isB = quad & 1;
        int d = isB ? 4 + dd : dd;
        bool valid = (!isB) || (dd < 2);
        int rr = row0 - PADW + hr;
        float v = 0.f;
        if (valid && rr >= lo && rr < hi) {
            int srcbase = (quad < 2) ? 48 : 96;
            v = qkv[(size_t)rr * N144 + srcbase + g * HD + d];
        }
        kv8[i] = v;
    }
    // ---- stage rel: [31][64] A|B layout ----
    for (int i = tid; i < KW * RELP8; i += 256) {
        int t = i >> 6, col = i & 63;
        int isB = col >> 5;
        int w = col & 31;
        int g = w >> 2, dd = w & 3;
        int d = isB ? 4 + dd : dd;
        bool valid = (!isB) || (dd < 2);
        relT[i] = valid ? rel[(g * HD + d) * KW + t] : 0.f;
    }
    for (int i = tid; i < OF * MC; i += 256) {
        int o = i / MC, c = i - o * MC;
        WoT[c * OF + o] = Wp[i];
    }
    if (tid < OF) boS[tid] = bp[tid];
    if (tid < MC) { lngS[tid] = lng[tid]; lnbS[tid] = lnb[tid]; }
    __syncthreads();

    // ---- per-(row, group) attention, softmax in registers ----
    {
        const int lrow = tid >> 3;     // 0..31
        const int g = tid & 7;
        const int row = row0 + lrow;
        const int gb = g * HD;

        float qr[8];
        {
            const float2* qp = reinterpret_cast<const float2*>(qkv + (size_t)row * N144 + gb);
            float2 a = qp[0], b = qp[1], c = qp[2];
            qr[0]=a.x; qr[1]=a.y; qr[2]=b.x; qr[3]=b.y; qr[4]=c.x; qr[5]=c.y;
            qr[6]=0.f; qr[7]=0.f;
        }

        float en[KW];
#pragma unroll
        for (int t = 0; t < KW; t++) {
            float4 ra = *reinterpret_cast<const float4*>(relT + t * RELP8 + g * 4);
            float4 rb = *reinterpret_cast<const float4*>(relT + t * RELP8 + 32 + g * 4);
            const float* kr = kv8 + (lrow + t) * KV8P;
            float4 ka = *reinterpret_cast<const float4*>(kr + g * 4);
            float4 kb = *reinterpret_cast<const float4*>(kr + 32 + g * 4);
            en[t] = dot8(qr, ra, rb) + dot8(qr, ka, kb);
        }

        float mx = en[0];
#pragma unroll
        for (int t = 1; t < KW; t++) mx = fmaxf(mx, en[t]);
        float ss = 0.f;
#pragma unroll
        for (int t = 0; t < KW; t++) { en[t] = __expf(en[t] - mx); ss += en[t]; }
        float inv = 1.f / ss;
#pragma unroll
        for (int t = 0; t < KW; t++) en[t] *= inv;

        float xv[8] = {0,0,0,0,0,0,0,0};
#pragma unroll
        for (int t = 0; t < KW; t++) {
            const float* vr = kv8 + (lrow + t) * KV8P;
            float4 va = *reinterpret_cast<const float4*>(vr + 64 + g * 4);
            float4 vb = *reinterpret_cast<const float4*>(vr + 96 + g * 4);
            float w = en[t];
            xv[0] = fmaf(w, va.x, xv[0]); xv[1] = fmaf(w, va.y, xv[1]);
            xv[2] = fmaf(w, va.z, xv[2]); xv[3] = fmaf(w, va.w, xv[3]);
            xv[4] = fmaf(w, vb.x, xv[4]); xv[5] = fmaf(w, vb.y, xv[5]);
            xv[6] = fmaf(w, vb.z, xv[6]); xv[7] = fmaf(w, vb.w, xv[7]);
        }

        // FIRST: stage attention weights into smem (reuse kv region after all
        // kv reads complete) for a coalesced a_out write later.
        if constexpr (FIRST) {
            __syncthreads();           // all warps done reading kv8
            float* abuf = sm + OFF_KV; // [32][248]: 32*248 = 7936 = KV size
#pragma unroll
            for (int t = 0; t < KW; t++)
                abuf[lrow * 248 + g * KW + t] = en[t];
        }

        // layernorm across 8 group-lanes (pad slots exactly zero)
        float a0 = 0.f, b0 = 0.f;
#pragma unroll
        for (int d = 0; d < 8; d++) { a0 += xv[d]; b0 = fmaf(xv[d], xv[d], b0); }
#pragma unroll
        for (int m = 1; m < 8; m <<= 1) {
            a0 += __shfl_xor_sync(0xffffffffu, a0, m);
            b0 += __shfl_xor_sync(0xffffffffu, b0, m);
        }
        float mu = a0 * (1.f / MC);
        float rstd = rsqrtf(b0 * (1.f / MC) - mu * mu + 1e-5f);
#pragma unroll
        for (int d = 0; d < HD; d++) {
            float v = (xv[d] - mu) * rstd * lngS[gb + d] + lnbS[gb + d];
            xs[lrow * XSP + gb + d] = v;
            if (FIRST) g_x2[(size_t)row * 136 + OF + gb + d] = v;
        }
    }
    __syncthreads();

    // FIRST: coalesced a_out write (layout matches [row][g][t] exactly)
    if constexpr (FIRST) {
        const float* abuf = sm + OFF_KV;
        float* dst = a_out + (size_t)row0 * 248;
        for (int i = tid; i < RPB * 248; i += 256) dst[i] = abuf[i];
    }

    // ---- projection + sigmoid: [32x48] x [48x88], 2x8 thread tiles ----
    if (tid < 176) {
        const int rq = tid / 11;       // 0..15 -> rows rq*2, rq*2+1
        const int o8 = tid - rq * 11;  // 0..10 -> cols o8*8..+7
        float acc[2][8];
#pragma unroll
        for (int j = 0; j < 8; j++) {
            float b = boS[o8 * 8 + j];
            acc[0][j] = b; acc[1][j] = b;
        }
#pragma unroll
        for (int c = 0; c < MC; c++) {
            float4 w0 = *reinterpret_cast<const float4*>(&WoT[c * OF + o8 * 8]);
            float4 w1 = *reinterpret_cast<const float4*>(&WoT[c * OF + o8 * 8 + 4]);
            float wv[8] = {w0.x, w0.y, w0.z, w0.w, w1.x, w1.y, w1.z, w1.w};
            float a0 = xs[(rq * 2) * XSP + c];
            float a1 = xs[(rq * 2 + 1) * XSP + c];
#pragma unroll
            for (int j = 0; j < 8; j++) {
                acc[0][j] = fmaf(a0, wv[j], acc[0][j]);
                acc[1][j] = fmaf(a1, wv[j], acc[1][j]);
            }
        }
#pragma unroll
        for (int r = 0; r < 2; r++) {
            int row = row0 + rq * 2 + r;
#pragma unroll
            for (int j = 0; j < 8; j++) {
                int o = o8 * 8 + j;
                float sig = 1.f / (1.f + __expf(-acc[r][j]));
                pred_out[(size_t)row * OF + o] = sig;
                if (FIRST) g_x2[(size_t)row * 136 + o] = sig;
            }
        }
    }
}

// ---------------- launch ----------------
extern "C" void kernel_launch(void* const* d_in, const int* in_sizes, int n_in,
                              void* d_out, int out_size)
{
    const float* spec = (const float*)d_in[0];
    const float* Wq1  = (const float*)d_in[1];
    const float* Wk1  = (const float*)d_in[2];
    const float* Wv1  = (const float*)d_in[3];
    const float* rel1 = (const float*)d_in[4];
    const float* ln1g = (const float*)d_in[5];
    const float* ln1b = (const float*)d_in[6];
    const float* Wo   = (const float*)d_in[7];
    const float* bo   = (const float*)d_in[8];
    const float* Wq2  = (const float*)d_in[9];
    const float* Wk2  = (const float*)d_in[10];
    const float* Wv2  = (const float*)d_in[11];
    const float* rel2 = (const float*)d_in[12];
    const float* ln2g = (const float*)d_in[13];
    const float* ln2b = (const float*)d_in[14];
    const float* Wf   = (const float*)d_in[15];
    const float* bf   = (const float*)d_in[16];

    float* out = (float*)d_out;
    float* frame = out;
    float* onset = out + (size_t)BS * OF;
    float* aout  = out + (size_t)2 * BS * OF;

    void* p_qkv1; cudaGetSymbolAddress(&p_qkv1, g_qkv1);
    void* p_x2;   cudaGetSymbolAddress(&p_x2, g_x2);
    void* p_qkv2; cudaGetSymbolAddress(&p_qkv2, g_qkv2);

    cudaFuncSetAttribute(attn_block<true>,
        cudaFuncAttributeMaxDynamicSharedMemorySize, SMEM_BYTES);
    cudaFuncSetAttribute(attn_block<false>,
        cudaFuncAttributeMaxDynamicSharedMemorySize, SMEM_BYTES);

    gemm_qkv<229><<<BS / 128, 192>>>(spec, Wq1, Wk1, Wv1, (float*)p_qkv1);
    attn_block<true><<<BS / RPB, 256, SMEM_BYTES>>>(
        rel1, ln1g, ln1b, Wo, bo, onset, aout);
    gemm_qkv<136><<<BS / 128, 192>>>((const float*)p_x2, Wq2, Wk2, Wv2,
                                     (float*)p_qkv2);
    attn_block<false><<<BS / RPB, 256, SMEM_BYTES>>>(
        rel2, ln2g, ln2b, Wf, bf, frame, nullptr);
}

// round 7
// speedup vs baseline: 1.0985x; 1.0985x over previous
#include <cuda_runtime.h>
#include <cuda_bf16.h>
#include <cstdint>

#define BATCH 8
#define SEQ   8192
#define BS    65536
#define MC    48
#define OF    88
#define NG    8
#define HD    6
#define KW    31
#define PADW  15
#define N144  144

// ---------------- device scratch ----------------
__device__ float g_qkv1[(size_t)BS * N144];
__device__ float g_x2  [(size_t)BS * 136];
__device__ float g_qkv2[(size_t)BS * N144];

// ---------------- fused QKV projection GEMM (round-5 best) ----------------
template <int K>
__global__ __launch_bounds__(256) void gemm_qkv(
    const float* __restrict__ x,
    const float* __restrict__ Wq, const float* __restrict__ Wk,
    const float* __restrict__ Wv,
    float* __restrict__ out)
{
    __shared__ float xs[128 * 16];    // [m][kk]
    __shared__ float ws[16 * 148];    // [kk][n] pitch 148

    const int tid = threadIdx.x;
    const int ty = tid >> 4;
    const int tx = tid & 15;
    const int row0 = blockIdx.x * 128;

    float acc[8][9];
#pragma unroll
    for (int r = 0; r < 8; r++)
#pragma unroll
        for (int c = 0; c < 9; c++) acc[r][c] = 0.f;

    float rx[8], rw[9];

    auto loadX = [&](int k0) {
#pragma unroll
        for (int j = 0; j < 8; j++) {
            int i = tid + j * 256;
            int m = i >> 4, kk = i & 15;
            int col = k0 + kk;
            rx[j] = (col < K) ? x[(size_t)(row0 + m) * K + col] : 0.f;
        }
    };
    auto loadW = [&](int k0) {
#pragma unroll
        for (int j = 0; j < 9; j++) {
            int i = tid + j * 256;
            int n = i >> 4, kk = i & 15;
            int col = k0 + kk;
            float w = 0.f;
            if (col < K) {
                const float* Wp; int nr;
                if (n < 48)      { Wp = Wq; nr = n; }
                else if (n < 96) { Wp = Wk; nr = n - 48; }
                else             { Wp = Wv; nr = n - 96; }
                w = Wp[nr * K + col];
            }
            rw[j] = w;
        }
    };

    loadX(0); loadW(0);

    for (int k0 = 0; k0 < K; k0 += 16) {
#pragma unroll
        for (int j = 0; j < 8; j++) xs[tid + j * 256] = rx[j];
#pragma unroll
        for (int j = 0; j < 9; j++) {
            int i = tid + j * 256;
            int n = i >> 4, kk = i & 15;
            ws[kk * 148 + n] = rw[j];
        }
        __syncthreads();

        if (k0 + 16 < K) { loadX(k0 + 16); loadW(k0 + 16); }

#pragma unroll
        for (int kk = 0; kk < 16; kk++) {
            float a[8], b[9];
#pragma unroll
            for (int r = 0; r < 8; r++) a[r] = xs[(ty * 8 + r) * 16 + kk];
#pragma unroll
            for (int c = 0; c < 9; c++) b[c] = ws[kk * 148 + tx * 9 + c];
#pragma unroll
            for (int r = 0; r < 8; r++)
#pragma unroll
                for (int c = 0; c < 9; c++)
                    acc[r][c] = fmaf(a[r], b[c], acc[r][c]);
        }
        __syncthreads();
    }
#pragma unroll
    for (int r = 0; r < 8; r++) {
        size_t o = (size_t)(row0 + ty * 8 + r) * N144 + tx * 9;
#pragma unroll
        for (int c = 0; c < 9; c++) out[o + c] = acc[r][c];
    }
}

// ---------------- attention + LN + sigmoid-proj ----------------
// Block: 64 rows, 256 threads. Thread = (row-pair, group): each k/v/rel
// LDS.128 pair serves TWO rows (overlapping windows) -> 93 LDS.128/row-pair.
// Layout per kv row (128 floats, 512B aligned): A_k[32]|B_k[32]|A_v[32]|B_v[32],
// channel c (g=c/6,d=c%6) at quad + g*4 + d (d<4) or B-quad g*4+(d-4); B pads 0.
constexpr int RPB  = 64;
constexpr int HALO = RPB + 2 * PADW;      // 94
constexpr int KV8P = 128;
constexpr int RELP8 = 64;
constexpr int XSP  = 49;

constexpr int OFF_KV  = 0;                          // [94][128] = 12032
constexpr int OFF_REL = OFF_KV + HALO * KV8P;       // [31][64]
constexpr int OFF_WOT = OFF_REL + KW * RELP8;       // [48][88] transposed
constexpr int OFF_XS  = OFF_WOT + MC * OF;          // [64][49]
constexpr int OFF_BO  = OFF_XS + RPB * XSP;
constexpr int OFF_LNG = OFF_BO + OF;
constexpr int OFF_LNB = OFF_LNG + MC;
constexpr int SMEM_F  = OFF_LNB + MC;
constexpr int SMEM_BYTES = SMEM_F * 4;              // ~86.5 KB -> 2 CTAs/SM

__device__ __forceinline__ float dot8(const float* q, float4 a, float4 b) {
    float e = q[0] * a.x;
    e = fmaf(q[1], a.y, e); e = fmaf(q[2], a.z, e); e = fmaf(q[3], a.w, e);
    e = fmaf(q[4], b.x, e); e = fmaf(q[5], b.y, e); e = fmaf(q[6], b.z, e);
    e = fmaf(q[7], b.w, e);
    return e;
}

template <bool FIRST>
__global__ __launch_bounds__(256, 2) void attn_block(
    const float* __restrict__ rel,
    const float* __restrict__ lng, const float* __restrict__ lnb,
    const float* __restrict__ Wp,      // [88,48]
    const float* __restrict__ bp,
    float* __restrict__ pred_out,      // [BS,88]
    float* __restrict__ a_out)         // [BS,248] (FIRST only)
{
    extern __shared__ __align__(16) float sm[];
    float* kv8  = sm + OFF_KV;
    float* relT = sm + OFF_REL;
    float* WoT  = sm + OFF_WOT;
    float* xs   = sm + OFF_XS;
    float* boS  = sm + OFF_BO;
    float* lngS = sm + OFF_LNG;
    float* lnbS = sm + OFF_LNB;

    const float* qkv = FIRST ? g_qkv1 : g_qkv2;

    const int tid = threadIdx.x;
    const int row0 = blockIdx.x * RPB;
    const int bi = row0 / SEQ;
    const int lo = bi * SEQ, hi = lo + SEQ;

    // ---- stage k/v (data + pads in one pass) ----
    for (int i = tid; i < HALO * KV8P; i += 256) {
        int hr = i >> 7, col = i & 127;
        int quad = col >> 5;            // 0:A_k 1:B_k 2:A_v 3:B_v
        int w = col & 31;
        int g = w >> 2, dd = w & 3;
        int isB = quad & 1;
        int d = isB ? 4 + dd : dd;
        bool valid = (!isB) || (dd < 2);
        int rr = row0 - PADW + hr;
        float v = 0.f;
        if (valid && rr >= lo && rr < hi) {
            int srcbase = (quad < 2) ? 48 : 96;
            v = qkv[(size_t)rr * N144 + srcbase + g * HD + d];
        }
        kv8[i] = v;
    }
    for (int i = tid; i < KW * RELP8; i += 256) {
        int t = i >> 6, col = i & 63;
        int isB = col >> 5;
        int w = col & 31;
        int g = w >> 2, dd = w & 3;
        int d = isB ? 4 + dd : dd;
        bool valid = (!isB) || (dd < 2);
        relT[i] = valid ? rel[(g * HD + d) * KW + t] : 0.f;
    }
    for (int i = tid; i < OF * MC; i += 256) {
        int o = i / MC, c = i - o * MC;
        WoT[c * OF + o] = Wp[i];
    }
    if (tid < OF) boS[tid] = bp[tid];
    if (tid < MC) { lngS[tid] = lng[tid]; lnbS[tid] = lnb[tid]; }
    __syncthreads();

    // ---- per-(row-pair, group) attention ----
    {
        const int pair = tid >> 3;     // 0..31
        const int g = tid & 7;
        const int lr0 = pair * 2;
        const int row0g = row0 + lr0;
        const int gb = g * HD;

        float qr0[8], qr1[8];
        {
            const float2* q0 = reinterpret_cast<const float2*>(qkv + (size_t)row0g * N144 + gb);
            const float2* q1 = reinterpret_cast<const float2*>(qkv + (size_t)(row0g + 1) * N144 + gb);
            float2 a = q0[0], b = q0[1], c = q0[2];
            qr0[0]=a.x; qr0[1]=a.y; qr0[2]=b.x; qr0[3]=b.y; qr0[4]=c.x; qr0[5]=c.y;
            qr0[6]=0.f; qr0[7]=0.f;
            a = q1[0]; b = q1[1]; c = q1[2];
            qr1[0]=a.x; qr1[1]=a.y; qr1[2]=b.x; qr1[3]=b.y; qr1[4]=c.x; qr1[5]=c.y;
            qr1[6]=0.f; qr1[7]=0.f;
        }

        float en0[KW], en1[KW];
        // rel term: one load pair serves both rows
#pragma unroll
        for (int t = 0; t < KW; t++) {
            float4 ra = *reinterpret_cast<const float4*>(relT + t * RELP8 + g * 4);
            float4 rb = *reinterpret_cast<const float4*>(relT + t * RELP8 + 32 + g * 4);
            en0[t] = dot8(qr0, ra, rb);
            en1[t] = dot8(qr1, ra, rb);
        }
        // qk band: k row j serves row0 (tap j) and row1 (tap j-1)
#pragma unroll
        for (int j = 0; j < 32; j++) {
            const float* kr = kv8 + (lr0 + j) * KV8P;
            float4 ka = *reinterpret_cast<const float4*>(kr + g * 4);
            float4 kb = *reinterpret_cast<const float4*>(kr + 32 + g * 4);
            if (j < 31) en0[j] += dot8(qr0, ka, kb);
            if (j > 0)  en1[j - 1] += dot8(qr1, ka, kb);
        }

        // softmax (registers)
        float mx0 = en0[0], mx1 = en1[0];
#pragma unroll
        for (int t = 1; t < KW; t++) { mx0 = fmaxf(mx0, en0[t]); mx1 = fmaxf(mx1, en1[t]); }
        float s0 = 0.f, s1 = 0.f;
#pragma unroll
        for (int t = 0; t < KW; t++) {
            en0[t] = __expf(en0[t] - mx0); s0 += en0[t];
            en1[t] = __expf(en1[t] - mx1); s1 += en1[t];
        }
        float i0 = 1.f / s0, i1 = 1.f / s1;
#pragma unroll
        for (int t = 0; t < KW; t++) { en0[t] *= i0; en1[t] *= i1; }

        if (FIRST) {
            float* ap0 = a_out + (size_t)row0g * 248 + g * KW;
            float* ap1 = ap0 + 248;
#pragma unroll
            for (int t = 0; t < KW; t++) { ap0[t] = en0[t]; ap1[t] = en1[t]; }
        }

        // attention-weighted V (one v load pair serves both rows)
        float xv0[8] = {0,0,0,0,0,0,0,0}, xv1[8] = {0,0,0,0,0,0,0,0};
#pragma unroll
        for (int j = 0; j < 32; j++) {
            const float* vr = kv8 + (lr0 + j) * KV8P;
            float4 va = *reinterpret_cast<const float4*>(vr + 64 + g * 4);
            float4 vb = *reinterpret_cast<const float4*>(vr + 96 + g * 4);
            float fv[8] = {va.x, va.y, va.z, va.w, vb.x, vb.y, vb.z, vb.w};
            if (j < 31) {
                float w = en0[j];
#pragma unroll
                for (int d = 0; d < 8; d++) xv0[d] = fmaf(w, fv[d], xv0[d]);
            }
            if (j > 0) {
                float w = en1[j - 1];
#pragma unroll
                for (int d = 0; d < 8; d++) xv1[d] = fmaf(w, fv[d], xv1[d]);
            }
        }

        // layernorm across 8 group-lanes (pad slots exactly zero)
        float a0 = 0.f, b0 = 0.f, a1 = 0.f, b1 = 0.f;
#pragma unroll
        for (int d = 0; d < 8; d++) {
            a0 += xv0[d]; b0 = fmaf(xv0[d], xv0[d], b0);
            a1 += xv1[d]; b1 = fmaf(xv1[d], xv1[d], b1);
        }
#pragma unroll
        for (int m = 1; m < 8; m <<= 1) {
            a0 += __shfl_xor_sync(0xffffffffu, a0, m);
            b0 += __shfl_xor_sync(0xffffffffu, b0, m);
            a1 += __shfl_xor_sync(0xffffffffu, a1, m);
            b1 += __shfl_xor_sync(0xffffffffu, b1, m);
        }
        float mu0 = a0 * (1.f / MC), mu1 = a1 * (1.f / MC);
        float r0 = rsqrtf(b0 * (1.f / MC) - mu0 * mu0 + 1e-5f);
        float r1 = rsqrtf(b1 * (1.f / MC) - mu1 * mu1 + 1e-5f);
#pragma unroll
        for (int d = 0; d < HD; d++) {
            float v0 = (xv0[d] - mu0) * r0 * lngS[gb + d] + lnbS[gb + d];
            float v1 = (xv1[d] - mu1) * r1 * lngS[gb + d] + lnbS[gb + d];
            xs[lr0 * XSP + gb + d] = v0;
            xs[(lr0 + 1) * XSP + gb + d] = v1;
            if (FIRST) {
                g_x2[(size_t)row0g * 136 + OF + gb + d] = v0;
                g_x2[(size_t)(row0g + 1) * 136 + OF + gb + d] = v1;
            }
        }
    }
    __syncthreads();

    // ---- projection + sigmoid: [64x48] x [48x88], 4x8 thread tiles ----
    if (tid < 176) {
        const int rq = tid / 11;       // 0..15 -> rows rq*4..+3
        const int o8 = tid - rq * 11;  // 0..10 -> cols o8*8..+7
        float acc[4][8];
#pragma unroll
        for (int j = 0; j < 8; j++) {
            float b = boS[o8 * 8 + j];
#pragma unroll
            for (int r = 0; r < 4; r++) acc[r][j] = b;
        }
#pragma unroll
        for (int c = 0; c < MC; c++) {
            float4 w0 = *reinterpret_cast<const float4*>(&WoT[c * OF + o8 * 8]);
            float4 w1 = *reinterpret_cast<const float4*>(&WoT[c * OF + o8 * 8 + 4]);
            float wv[8] = {w0.x, w0.y, w0.z, w0.w, w1.x, w1.y, w1.z, w1.w};
#pragma unroll
            for (int r = 0; r < 4; r++) {
                float a = xs[(rq * 4 + r) * XSP + c];
#pragma unroll
                for (int j = 0; j < 8; j++)
                    acc[r][j] = fmaf(a, wv[j], acc[r][j]);
            }
        }
#pragma unroll
        for (int r = 0; r < 4; r++) {
            int row = row0 + rq * 4 + r;
#pragma unroll
            for (int j = 0; j < 8; j++) {
                int o = o8 * 8 + j;
                float sig = 1.f / (1.f + __expf(-acc[r][j]));
                pred_out[(size_t)row * OF + o] = sig;
                if (FIRST) g_x2[(size_t)row * 136 + o] = sig;
            }
        }
    }
}

// ---------------- launch ----------------
extern "C" void kernel_launch(void* const* d_in, const int* in_sizes, int n_in,
                              void* d_out, int out_size)
{
    const float* spec = (const float*)d_in[0];
    const float* Wq1  = (const float*)d_in[1];
    const float* Wk1  = (const float*)d_in[2];
    const float* Wv1  = (const float*)d_in[3];
    const float* rel1 = (const float*)d_in[4];
    const float* ln1g = (const float*)d_in[5];
    const float* ln1b = (const float*)d_in[6];
    const float* Wo   = (const float*)d_in[7];
    const float* bo   = (const float*)d_in[8];
    const float* Wq2  = (const float*)d_in[9];
    const float* Wk2  = (const float*)d_in[10];
    const float* Wv2  = (const float*)d_in[11];
    const float* rel2 = (const float*)d_in[12];
    const float* ln2g = (const float*)d_in[13];
    const float* ln2b = (const float*)d_in[14];
    const float* Wf   = (const float*)d_in[15];
    const float* bf   = (const float*)d_in[16];

    float* out = (float*)d_out;
    float* frame = out;
    float* onset = out + (size_t)BS * OF;
    float* aout  = out + (size_t)2 * BS * OF;

    void* p_qkv1; cudaGetSymbolAddress(&p_qkv1, g_qkv1);
    void* p_x2;   cudaGetSymbolAddress(&p_x2, g_x2);
    void* p_qkv2; cudaGetSymbolAddress(&p_qkv2, g_qkv2);

    cudaFuncSetAttribute(attn_block<true>,
        cudaFuncAttributeMaxDynamicSharedMemorySize, SMEM_BYTES);
    cudaFuncSetAttribute(attn_block<false>,
        cudaFuncAttributeMaxDynamicSharedMemorySize, SMEM_BYTES);

    gemm_qkv<229><<<BS / 128, 256>>>(spec, Wq1, Wk1, Wv1, (float*)p_qkv1);
    attn_block<true><<<BS / RPB, 256, SMEM_BYTES>>>(
        rel1, ln1g, ln1b, Wo, bo, onset, aout);
    gemm_qkv<136><<<BS / 128, 256>>>((const float*)p_x2, Wq2, Wk2, Wv2,
                                     (float*)p_qkv2);
    attn_block<false><<<BS / RPB, 256, SMEM_BYTES>>>(
        rel2, ln2g, ln2b, Wf, bf, frame, nullptr);
}

// round 14
// speedup vs baseline: 1.1832x; 1.0771x over previous
#include <cuda_runtime.h>
#include <cuda_bf16.h>
#include <cstdint>

#define BATCH 8
#define SEQ   8192
#define BS    65536
#define MC    48
#define OF    88
#define NG    8
#define HD    6
#define KW    31
#define PADW  15
#define N144  144

// ---------------- device scratch ----------------
__device__ float g_qkv1[(size_t)BS * N144];
__device__ float g_x2  [(size_t)BS * 136];
__device__ float g_qkv2[(size_t)BS * N144];

// ============ bf16 split-precision mma.sync GEMM ============
// C[128 x 144] = X[128 x K] * W^T, W = [Wq;Wk;Wv] rows.
// D = Xhi*Whi + Xlo*Whi + Xhi*Wlo (fp32 acc). mma.sync.m16n8k16.bf16.
__device__ __forceinline__ void mma_bf16(float& c0, float& c1, float& c2, float& c3,
                                         uint32_t a0, uint32_t a1, uint32_t a2, uint32_t a3,
                                         uint32_t b0, uint32_t b1) {
    asm volatile(
        "mma.sync.aligned.m16n8k16.row.col.f32.bf16.bf16.f32 "
        "{%0,%1,%2,%3}, {%4,%5,%6,%7}, {%8,%9}, {%0,%1,%2,%3};"
        : "+f"(c0), "+f"(c1), "+f"(c2), "+f"(c3)
        : "r"(a0), "r"(a1), "r"(a2), "r"(a3), "r"(b0), "r"(b1));
}

constexpr int KT   = 48;   // K-chunk
constexpr int KTP  = 56;   // bf16 pitch (28 words: conflict-free frag loads)
constexpr int KTPW = 28;   // pitch in 32-bit words
constexpr int GSM_A = 128 * KTP;          // bf16 elems per A buffer
constexpr int GSM_B = 144 * KTP;
constexpr int GEMM_SMEM = (2 * GSM_A + 2 * GSM_B) * 2;   // 60,928 bytes

template <int KSRC, int NCHUNK>
__global__ __launch_bounds__(256, 2) void gemm_qkv_mma(
    const float* __restrict__ x,
    const float* __restrict__ Wq, const float* __restrict__ Wk,
    const float* __restrict__ Wv,
    float* __restrict__ out)
{
    extern __shared__ __align__(16) char smem[];
    uint16_t* Ahi = reinterpret_cast<uint16_t*>(smem);
    uint16_t* Alo = Ahi + GSM_A;
    uint16_t* Bhi = Alo + GSM_A;
    uint16_t* Blo = Bhi + GSM_B;
    const uint32_t* Ahi32 = reinterpret_cast<const uint32_t*>(Ahi);
    const uint32_t* Alo32 = reinterpret_cast<const uint32_t*>(Alo);
    const uint32_t* Bhi32 = reinterpret_cast<const uint32_t*>(Bhi);
    const uint32_t* Blo32 = reinterpret_cast<const uint32_t*>(Blo);

    const int tid  = threadIdx.x;
    const int wid  = tid >> 5;
    const int lane = tid & 31;
    const int row0 = blockIdx.x * 128;

    float acc[18][4];
#pragma unroll
    for (int nt = 0; nt < 18; nt++)
#pragma unroll
        for (int j = 0; j < 4; j++) acc[nt][j] = 0.f;

    for (int c = 0; c < NCHUNK; c++) {
        const int kbase = c * KT;
        __syncthreads();   // previous chunk's reads done
        // ---- stage A (hi/lo) ----
        for (int i = tid; i < 128 * KT; i += 256) {
            int m = i / KT, k = i - m * KT;
            int kg = kbase + k;
            float v = (kg < KSRC) ? x[(size_t)(row0 + m) * KSRC + kg] : 0.f;
            __nv_bfloat16 hi = __float2bfloat16_rn(v);
            __nv_bfloat16 lo = __float2bfloat16_rn(v - __bfloat162float(hi));
            Ahi[m * KTP + k] = *reinterpret_cast<uint16_t*>(&hi);
            Alo[m * KTP + k] = *reinterpret_cast<uint16_t*>(&lo);
        }
        // ---- stage B (hi/lo) ----
        for (int i = tid; i < 144 * KT; i += 256) {
            int n = i / KT, k = i - n * KT;
            int kg = kbase + k;
            float v = 0.f;
            if (kg < KSRC) {
                const float* Wp; int nr;
                if (n < 48)      { Wp = Wq; nr = n; }
                else if (n < 96) { Wp = Wk; nr = n - 48; }
                else             { Wp = Wv; nr = n - 96; }
                v = Wp[nr * KSRC + kg];
            }
            __nv_bfloat16 hi = __float2bfloat16_rn(v);
            __nv_bfloat16 lo = __float2bfloat16_rn(v - __bfloat162float(hi));
            Bhi[n * KTP + k] = *reinterpret_cast<uint16_t*>(&hi);
            Blo[n * KTP + k] = *reinterpret_cast<uint16_t*>(&lo);
        }
        __syncthreads();

        const int arow = wid * 16 + (lane >> 2);
        const int kq = lane & 3;
#pragma unroll
        for (int ks = 0; ks < KT / 16; ks++) {
            const int ab = arow * KTPW + ks * 8 + kq;
            uint32_t ah0 = Ahi32[ab];
            uint32_t ah1 = Ahi32[ab + 8 * KTPW];
            uint32_t ah2 = Ahi32[ab + 4];
            uint32_t ah3 = Ahi32[ab + 8 * KTPW + 4];
            uint32_t al0 = Alo32[ab];
            uint32_t al1 = Alo32[ab + 8 * KTPW];
            uint32_t al2 = Alo32[ab + 4];
            uint32_t al3 = Alo32[ab + 8 * KTPW + 4];
            const int bb = (lane >> 2) * KTPW + ks * 8 + kq;
#pragma unroll
            for (int nt = 0; nt < 18; nt++) {
                const int bi = bb + nt * 8 * KTPW;
                uint32_t bh0 = Bhi32[bi], bh1 = Bhi32[bi + 4];
                uint32_t bl0 = Blo32[bi], bl1 = Blo32[bi + 4];
                mma_bf16(acc[nt][0], acc[nt][1], acc[nt][2], acc[nt][3],
                         ah0, ah1, ah2, ah3, bh0, bh1);
                mma_bf16(acc[nt][0], acc[nt][1], acc[nt][2], acc[nt][3],
                         al0, al1, al2, al3, bh0, bh1);
                mma_bf16(acc[nt][0], acc[nt][1], acc[nt][2], acc[nt][3],
                         ah0, ah1, ah2, ah3, bl0, bl1);
            }
        }
    }

    // ---- epilogue: c0,c1 -> (row, n..n+1); c2,c3 -> (row+8, n..n+1) ----
    const int r0 = row0 + wid * 16 + (lane >> 2);
    const int cb = (lane & 3) * 2;
#pragma unroll
    for (int nt = 0; nt < 18; nt++) {
        int n = nt * 8 + cb;
        *reinterpret_cast<float2*>(&out[(size_t)r0 * N144 + n]) =
            make_float2(acc[nt][0], acc[nt][1]);
        *reinterpret_cast<float2*>(&out[(size_t)(r0 + 8) * N144 + n]) =
            make_float2(acc[nt][2], acc[nt][3]);
    }
}

// ---------------- attention + LN + sigmoid-proj (round-7, unchanged) -------
constexpr int RPB  = 64;
constexpr int HALO = RPB + 2 * PADW;      // 94
constexpr int KV8P = 128;
constexpr int RELP8 = 64;
constexpr int XSP  = 49;

constexpr int OFF_KV  = 0;
constexpr int OFF_REL = OFF_KV + HALO * KV8P;
constexpr int OFF_WOT = OFF_REL + KW * RELP8;
constexpr int OFF_XS  = OFF_WOT + MC * OF;
constexpr int OFF_BO  = OFF_XS + RPB * XSP;
constexpr int OFF_LNG = OFF_BO + OF;
constexpr int OFF_LNB = OFF_LNG + MC;
constexpr int SMEM_F  = OFF_LNB + MC;
constexpr int SMEM_BYTES = SMEM_F * 4;

__device__ __forceinline__ float dot8(const float* q, float4 a, float4 b) {
    float e = q[0] * a.x;
    e = fmaf(q[1], a.y, e); e = fmaf(q[2], a.z, e); e = fmaf(q[3], a.w, e);
    e = fmaf(q[4], b.x, e); e = fmaf(q[5], b.y, e); e = fmaf(q[6], b.z, e);
    e = fmaf(q[7], b.w, e);
    return e;
}

template <bool FIRST>
__global__ __launch_bounds__(256, 2) void attn_block(
    const float* __restrict__ rel,
    const float* __restrict__ lng, const float* __restrict__ lnb,
    const float* __restrict__ Wp,
    const float* __restrict__ bp,
    float* __restrict__ pred_out,
    float* __restrict__ a_out)
{
    extern __shared__ __align__(16) float sm[];
    float* kv8  = sm + OFF_KV;
    float* relT = sm + OFF_REL;
    float* WoT  = sm + OFF_WOT;
    float* xs   = sm + OFF_XS;
    float* boS  = sm + OFF_BO;
    float* lngS = sm + OFF_LNG;
    float* lnbS = sm + OFF_LNB;

    const float* qkv = FIRST ? g_qkv1 : g_qkv2;

    const int tid = threadIdx.x;
    const int row0 = blockIdx.x * RPB;
    const int bi = row0 / SEQ;
    const int lo = bi * SEQ, hi = lo + SEQ;

    for (int i = tid; i < HALO * KV8P; i += 256) {
        int hr = i >> 7, col = i & 127;
        int quad = col >> 5;
        int w = col & 31;
        int g = w >> 2, dd = w & 3;
        int isB = quad & 1;
        int d = isB ? 4 + dd : dd;
        bool valid = (!isB) || (dd < 2);
        int rr = row0 - PADW + hr;
        float v = 0.f;
        if (valid && rr >= lo && rr < hi) {
            int srcbase = (quad < 2) ? 48 : 96;
            v = qkv[(size_t)rr * N144 + srcbase + g * HD + d];
        }
        kv8[i] = v;
    }
    for (int i = tid; i < KW * RELP8; i += 256) {
        int t = i >> 6, col = i & 63;
        int isB = col >> 5;
        int w = col & 31;
        int g = w >> 2, dd = w & 3;
        int d = isB ? 4 + dd : dd;
        bool valid = (!isB) || (dd < 2);
        relT[i] = valid ? rel[(g * HD + d) * KW + t] : 0.f;
    }
    for (int i = tid; i < OF * MC; i += 256) {
        int o = i / MC, c = i - o * MC;
        WoT[c * OF + o] = Wp[i];
    }
    if (tid < OF) boS[tid] = bp[tid];
    if (tid < MC) { lngS[tid] = lng[tid]; lnbS[tid] = lnb[tid]; }
    __syncthreads();

    {
        const int pair = tid >> 3;
        const int g = tid & 7;
        const int lr0 = pair * 2;
        const int row0g = row0 + lr0;
        const int gb = g * HD;

        float qr0[8], qr1[8];
        {
            const float2* q0 = reinterpret_cast<const float2*>(qkv + (size_t)row0g * N144 + gb);
            const float2* q1 = reinterpret_cast<const float2*>(qkv + (size_t)(row0g + 1) * N144 + gb);
            float2 a = q0[0], b = q0[1], c = q0[2];
            qr0[0]=a.x; qr0[1]=a.y; qr0[2]=b.x; qr0[3]=b.y; qr0[4]=c.x; qr0[5]=c.y;
            qr0[6]=0.f; qr0[7]=0.f;
            a = q1[0]; b = q1[1]; c = q1[2];
            qr1[0]=a.x; qr1[1]=a.y; qr1[2]=b.x; qr1[3]=b.y; qr1[4]=c.x; qr1[5]=c.y;
            qr1[6]=0.f; qr1[7]=0.f;
        }

        float en0[KW], en1[KW];
#pragma unroll
        for (int t = 0; t < KW; t++) {
            float4 ra = *reinterpret_cast<const float4*>(relT + t * RELP8 + g * 4);
            float4 rb = *reinterpret_cast<const float4*>(relT + t * RELP8 + 32 + g * 4);
            en0[t] = dot8(qr0, ra, rb);
            en1[t] = dot8(qr1, ra, rb);
        }
#pragma unroll
        for (int j = 0; j < 32; j++) {
            const float* kr = kv8 + (lr0 + j) * KV8P;
            float4 ka = *reinterpret_cast<const float4*>(kr + g * 4);
            float4 kb = *reinterpret_cast<const float4*>(kr + 32 + g * 4);
            if (j < 31) en0[j] += dot8(qr0, ka, kb);
            if (j > 0)  en1[j - 1] += dot8(qr1, ka, kb);
        }

        float mx0 = en0[0], mx1 = en1[0];
#pragma unroll
        for (int t = 1; t < KW; t++) { mx0 = fmaxf(mx0, en0[t]); mx1 = fmaxf(mx1, en1[t]); }
        float s0 = 0.f, s1 = 0.f;
#pragma unroll
        for (int t = 0; t < KW; t++) {
            en0[t] = __expf(en0[t] - mx0); s0 += en0[t];
            en1[t] = __expf(en1[t] - mx1); s1 += en1[t];
        }
        float i0 = 1.f / s0, i1 = 1.f / s1;
#pragma unroll
        for (int t = 0; t < KW; t++) { en0[t] *= i0; en1[t] *= i1; }

        if (FIRST) {
            float* ap0 = a_out + (size_t)row0g * 248 + g * KW;
            float* ap1 = ap0 + 248;
#pragma unroll
            for (int t = 0; t < KW; t++) { ap0[t] = en0[t]; ap1[t] = en1[t]; }
        }

        float xv0[8] = {0,0,0,0,0,0,0,0}, xv1[8] = {0,0,0,0,0,0,0,0};
#pragma unroll
        for (int j = 0; j < 32; j++) {
            const float* vr = kv8 + (lr0 + j) * KV8P;
            float4 va = *reinterpret_cast<const float4*>(vr + 64 + g * 4);
            float4 vb = *reinterpret_cast<const float4*>(vr + 96 + g * 4);
            float fv[8] = {va.x, va.y, va.z, va.w, vb.x, vb.y, vb.z, vb.w};
            if (j < 31) {
                float w = en0[j];
#pragma unroll
                for (int d = 0; d < 8; d++) xv0[d] = fmaf(w, fv[d], xv0[d]);
            }
            if (j > 0) {
                float w = en1[j - 1];
#pragma unroll
                for (int d = 0; d < 8; d++) xv1[d] = fmaf(w, fv[d], xv1[d]);
            }
        }

        float a0 = 0.f, b0 = 0.f, a1 = 0.f, b1 = 0.f;
#pragma unroll
        for (int d = 0; d < 8; d++) {
            a0 += xv0[d]; b0 = fmaf(xv0[d], xv0[d], b0);
            a1 += xv1[d]; b1 = fmaf(xv1[d], xv1[d], b1);
        }
#pragma unroll
        for (int m = 1; m < 8; m <<= 1) {
            a0 += __shfl_xor_sync(0xffffffffu, a0, m);
            b0 += __shfl_xor_sync(0xffffffffu, b0, m);
            a1 += __shfl_xor_sync(0xffffffffu, a1, m);
            b1 += __shfl_xor_sync(0xffffffffu, b1, m);
        }
        float mu0 = a0 * (1.f / MC), mu1 = a1 * (1.f / MC);
        float r0 = rsqrtf(b0 * (1.f / MC) - mu0 * mu0 + 1e-5f);
        float r1 = rsqrtf(b1 * (1.f / MC) - mu1 * mu1 + 1e-5f);
#pragma unroll
        for (int d = 0; d < HD; d++) {
            float v0 = (xv0[d] - mu0) * r0 * lngS[gb + d] + lnbS[gb + d];
            float v1 = (xv1[d] - mu1) * r1 * lngS[gb + d] + lnbS[gb + d];
            xs[lr0 * XSP + gb + d] = v0;
            xs[(lr0 + 1) * XSP + gb + d] = v1;
            if (FIRST) {
                g_x2[(size_t)row0g * 136 + OF + gb + d] = v0;
                g_x2[(size_t)(row0g + 1) * 136 + OF + gb + d] = v1;
            }
        }
    }
    __syncthreads();

    if (tid < 176) {
        const int rq = tid / 11;
        const int o8 = tid - rq * 11;
        float acc[4][8];
#pragma unroll
        for (int j = 0; j < 8; j++) {
            float b = boS[o8 * 8 + j];
#pragma unroll
            for (int r = 0; r < 4; r++) acc[r][j] = b;
        }
#pragma unroll
        for (int c = 0; c < MC; c++) {
            float4 w0 = *reinterpret_cast<const float4*>(&WoT[c * OF + o8 * 8]);
            float4 w1 = *reinterpret_cast<const float4*>(&WoT[c * OF + o8 * 8 + 4]);
            float wv[8] = {w0.x, w0.y, w0.z, w0.w, w1.x, w1.y, w1.z, w1.w};
#pragma unroll
            for (int r = 0; r < 4; r++) {
                float a = xs[(rq * 4 + r) * XSP + c];
#pragma unroll
                for (int j = 0; j < 8; j++)
                    acc[r][j] = fmaf(a, wv[j], acc[r][j]);
            }
        }
#pragma unroll
        for (int r = 0; r < 4; r++) {
            int row = row0 + rq * 4 + r;
#pragma unroll
            for (int j = 0; j < 8; j++) {
                int o = o8 * 8 + j;
                float sig = 1.f / (1.f + __expf(-acc[r][j]));
                pred_out[(size_t)row * OF + o] = sig;
                if (FIRST) g_x2[(size_t)row * 136 + o] = sig;
            }
        }
    }
}

// ---------------- launch ----------------
extern "C" void kernel_launch(void* const* d_in, const int* in_sizes, int n_in,
                              void* d_out, int out_size)
{
    const float* spec = (const float*)d_in[0];
    const float* Wq1  = (const float*)d_in[1];
    const float* Wk1  = (const float*)d_in[2];
    const float* Wv1  = (const float*)d_in[3];
    const float* rel1 = (const float*)d_in[4];
    const float* ln1g = (const float*)d_in[5];
    const float* ln1b = (const float*)d_in[6];
    const float* Wo   = (const float*)d_in[7];
    const float* bo   = (const float*)d_in[8];
    const float* Wq2  = (const float*)d_in[9];
    const float* Wk2  = (const float*)d_in[10];
    const float* Wv2  = (const float*)d_in[11];
    const float* rel2 = (const float*)d_in[12];
    const float* ln2g = (const float*)d_in[13];
    const float* ln2b = (const float*)d_in[14];
    const float* Wf   = (const float*)d_in[15];
    const float* bf   = (const float*)d_in[16];

    float* out = (float*)d_out;
    float* frame = out;
    float* onset = out + (size_t)BS * OF;
    float* aout  = out + (size_t)2 * BS * OF;

    void* p_qkv1; cudaGetSymbolAddress(&p_qkv1, g_qkv1);
    void* p_x2;   cudaGetSymbolAddress(&p_x2, g_x2);
    void* p_qkv2; cudaGetSymbolAddress(&p_qkv2, g_qkv2);

    cudaFuncSetAttribute(gemm_qkv_mma<229, 5>,
        cudaFuncAttributeMaxDynamicSharedMemorySize, GEMM_SMEM);
    cudaFuncSetAttribute(gemm_qkv_mma<136, 3>,
        cudaFuncAttributeMaxDynamicSharedMemorySize, GEMM_SMEM);
    cudaFuncSetAttribute(attn_block<true>,
        cudaFuncAttributeMaxDynamicSharedMemorySize, SMEM_BYTES);
    cudaFuncSetAttribute(attn_block<false>,
        cudaFuncAttributeMaxDynamicSharedMemorySize, SMEM_BYTES);

    gemm_qkv_mma<229, 5><<<BS / 128, 256, GEMM_SMEM>>>(spec, Wq1, Wk1, Wv1,
                                                       (float*)p_qkv1);
    attn_block<true><<<BS / RPB, 256, SMEM_BYTES>>>(
        rel1, ln1g, ln1b, Wo, bo, onset, aout);
    gemm_qkv_mma<136, 3><<<BS / 128, 256, GEMM_SMEM>>>((const float*)p_x2,
                                                       Wq2, Wk2, Wv2,
                                                       (float*)p_qkv2);
    attn_block<false><<<BS / RPB, 256, SMEM_BYTES>>>(
        rel2, ln2g, ln2b, Wf, bf, frame, nullptr);
}

// round 15
// speedup vs baseline: 1.3639x; 1.1527x over previous
#include <cuda_runtime.h>
#include <cuda_bf16.h>
#include <cstdint>

#define BATCH 8
#define SEQ   8192
#define BS    65536
#define MC    48
#define OF    88
#define NG    8
#define HD    6
#define KW    31
#define PADW  15
#define N144  144

// ---------------- device scratch ----------------
__device__ float g_qkv1[(size_t)BS * N144];
__device__ float g_x2  [(size_t)BS * 136];
__device__ float g_qkv2[(size_t)BS * N144];

// ============ bf16 split-precision mma.sync GEMM (round-14, passing) ======
__device__ __forceinline__ void mma_bf16(float& c0, float& c1, float& c2, float& c3,
                                         uint32_t a0, uint32_t a1, uint32_t a2, uint32_t a3,
                                         uint32_t b0, uint32_t b1) {
    asm volatile(
        "mma.sync.aligned.m16n8k16.row.col.f32.bf16.bf16.f32 "
        "{%0,%1,%2,%3}, {%4,%5,%6,%7}, {%8,%9}, {%0,%1,%2,%3};"
        : "+f"(c0), "+f"(c1), "+f"(c2), "+f"(c3)
        : "r"(a0), "r"(a1), "r"(a2), "r"(a3), "r"(b0), "r"(b1));
}

constexpr int KT   = 48;
constexpr int KTP  = 56;
constexpr int KTPW = 28;
constexpr int GSM_A = 128 * KTP;
constexpr int GSM_B = 144 * KTP;
constexpr int GEMM_SMEM = (2 * GSM_A + 2 * GSM_B) * 2;

template <int KSRC, int NCHUNK>
__global__ __launch_bounds__(256, 2) void gemm_qkv_mma(
    const float* __restrict__ x,
    const float* __restrict__ Wq, const float* __restrict__ Wk,
    const float* __restrict__ Wv,
    float* __restrict__ out)
{
    extern __shared__ __align__(16) char smem[];
    uint16_t* Ahi = reinterpret_cast<uint16_t*>(smem);
    uint16_t* Alo = Ahi + GSM_A;
    uint16_t* Bhi = Alo + GSM_A;
    uint16_t* Blo = Bhi + GSM_B;
    const uint32_t* Ahi32 = reinterpret_cast<const uint32_t*>(Ahi);
    const uint32_t* Alo32 = reinterpret_cast<const uint32_t*>(Alo);
    const uint32_t* Bhi32 = reinterpret_cast<const uint32_t*>(Bhi);
    const uint32_t* Blo32 = reinterpret_cast<const uint32_t*>(Blo);

    const int tid  = threadIdx.x;
    const int wid  = tid >> 5;
    const int lane = tid & 31;
    const int row0 = blockIdx.x * 128;

    float acc[18][4];
#pragma unroll
    for (int nt = 0; nt < 18; nt++)
#pragma unroll
        for (int j = 0; j < 4; j++) acc[nt][j] = 0.f;

    for (int c = 0; c < NCHUNK; c++) {
        const int kbase = c * KT;
        __syncthreads();
        for (int i = tid; i < 128 * KT; i += 256) {
            int m = i / KT, k = i - m * KT;
            int kg = kbase + k;
            float v = (kg < KSRC) ? x[(size_t)(row0 + m) * KSRC + kg] : 0.f;
            __nv_bfloat16 hi = __float2bfloat16_rn(v);
            __nv_bfloat16 lo = __float2bfloat16_rn(v - __bfloat162float(hi));
            Ahi[m * KTP + k] = *reinterpret_cast<uint16_t*>(&hi);
            Alo[m * KTP + k] = *reinterpret_cast<uint16_t*>(&lo);
        }
        for (int i = tid; i < 144 * KT; i += 256) {
            int n = i / KT, k = i - n * KT;
            int kg = kbase + k;
            float v = 0.f;
            if (kg < KSRC) {
                const float* Wp; int nr;
                if (n < 48)      { Wp = Wq; nr = n; }
                else if (n < 96) { Wp = Wk; nr = n - 48; }
                else             { Wp = Wv; nr = n - 96; }
                v = Wp[nr * KSRC + kg];
            }
            __nv_bfloat16 hi = __float2bfloat16_rn(v);
            __nv_bfloat16 lo = __float2bfloat16_rn(v - __bfloat162float(hi));
            Bhi[n * KTP + k] = *reinterpret_cast<uint16_t*>(&hi);
            Blo[n * KTP + k] = *reinterpret_cast<uint16_t*>(&lo);
        }
        __syncthreads();

        const int arow = wid * 16 + (lane >> 2);
        const int kq = lane & 3;
#pragma unroll
        for (int ks = 0; ks < KT / 16; ks++) {
            const int ab = arow * KTPW + ks * 8 + kq;
            uint32_t ah0 = Ahi32[ab];
            uint32_t ah1 = Ahi32[ab + 8 * KTPW];
            uint32_t ah2 = Ahi32[ab + 4];
            uint32_t ah3 = Ahi32[ab + 8 * KTPW + 4];
            uint32_t al0 = Alo32[ab];
            uint32_t al1 = Alo32[ab + 8 * KTPW];
            uint32_t al2 = Alo32[ab + 4];
            uint32_t al3 = Alo32[ab + 8 * KTPW + 4];
            const int bb = (lane >> 2) * KTPW + ks * 8 + kq;
#pragma unroll
            for (int nt = 0; nt < 18; nt++) {
                const int bi = bb + nt * 8 * KTPW;
                uint32_t bh0 = Bhi32[bi], bh1 = Bhi32[bi + 4];
                uint32_t bl0 = Blo32[bi], bl1 = Blo32[bi + 4];
                mma_bf16(acc[nt][0], acc[nt][1], acc[nt][2], acc[nt][3],
                         ah0, ah1, ah2, ah3, bh0, bh1);
                mma_bf16(acc[nt][0], acc[nt][1], acc[nt][2], acc[nt][3],
                         al0, al1, al2, al3, bh0, bh1);
                mma_bf16(acc[nt][0], acc[nt][1], acc[nt][2], acc[nt][3],
                         ah0, ah1, ah2, ah3, bl0, bl1);
            }
        }
    }

    const int r0 = row0 + wid * 16 + (lane >> 2);
    const int cb = (lane & 3) * 2;
#pragma unroll
    for (int nt = 0; nt < 18; nt++) {
        int n = nt * 8 + cb;
        *reinterpret_cast<float2*>(&out[(size_t)r0 * N144 + n]) =
            make_float2(acc[nt][0], acc[nt][1]);
        *reinterpret_cast<float2*>(&out[(size_t)(r0 + 8) * N144 + n]) =
            make_float2(acc[nt][2], acc[nt][3]);
    }
}

// ---------------- attention + LN + sigmoid-proj ----------------
// Round-7 compute core + smem-staged coalesced outputs (a_out, pred, g_x2).
constexpr int RPB  = 64;
constexpr int HALO = RPB + 2 * PADW;      // 94
constexpr int KV8P = 128;
constexpr int RELP8 = 64;
constexpr int XSP  = 52;                   // float4-aligned pitch

constexpr int OFF_KV  = 0;                          // [94][128] = 12032 (reused as abuf/sigbuf)
constexpr int OFF_REL = OFF_KV + HALO * KV8P;       // 12032
constexpr int OFF_WOT = OFF_REL + KW * RELP8;       // 14016
constexpr int OFF_XS  = OFF_WOT + MC * OF;          // 18240 [64][52]
constexpr int OFF_BO  = OFF_XS + RPB * XSP;         // 21568
constexpr int OFF_LNG = OFF_BO + OF;
constexpr int OFF_LNB = OFF_LNG + MC;
constexpr int SMEM_F  = OFF_LNB + MC;               // 21752
constexpr int SMEM_BYTES = SMEM_F * 4;              // 87008 -> 2 CTAs/SM

__device__ __forceinline__ float dot8(const float* q, float4 a, float4 b) {
    float e = q[0] * a.x;
    e = fmaf(q[1], a.y, e); e = fmaf(q[2], a.z, e); e = fmaf(q[3], a.w, e);
    e = fmaf(q[4], b.x, e); e = fmaf(q[5], b.y, e); e = fmaf(q[6], b.z, e);
    e = fmaf(q[7], b.w, e);
    return e;
}

template <bool FIRST>
__global__ __launch_bounds__(256, 2) void attn_block(
    const float* __restrict__ rel,
    const float* __restrict__ lng, const float* __restrict__ lnb,
    const float* __restrict__ Wp,
    const float* __restrict__ bp,
    float* __restrict__ pred_out,
    float* __restrict__ a_out)
{
    extern __shared__ __align__(16) float sm[];
    float* kv8  = sm + OFF_KV;
    float* relT = sm + OFF_REL;
    float* WoT  = sm + OFF_WOT;
    float* xs   = sm + OFF_XS;
    float* boS  = sm + OFF_BO;
    float* lngS = sm + OFF_LNG;
    float* lnbS = sm + OFF_LNB;

    const float* qkv = FIRST ? g_qkv1 : g_qkv2;

    const int tid = threadIdx.x;
    const int row0 = blockIdx.x * RPB;
    const int bi = row0 / SEQ;
    const int lo = bi * SEQ, hi = lo + SEQ;

    // ---- stage k/v (A/B-split layout, aligned pitch) ----
    for (int i = tid; i < HALO * KV8P; i += 256) {
        int hr = i >> 7, col = i & 127;
        int quad = col >> 5;
        int w = col & 31;
        int g = w >> 2, dd = w & 3;
        int isB = quad & 1;
        int d = isB ? 4 + dd : dd;
        bool valid = (!isB) || (dd < 2);
        int rr = row0 - PADW + hr;
        float v = 0.f;
        if (valid && rr >= lo && rr < hi) {
            int srcbase = (quad < 2) ? 48 : 96;
            v = qkv[(size_t)rr * N144 + srcbase + g * HD + d];
        }
        kv8[i] = v;
    }
    for (int i = tid; i < KW * RELP8; i += 256) {
        int t = i >> 6, col = i & 63;
        int isB = col >> 5;
        int w = col & 31;
        int g = w >> 2, dd = w & 3;
        int d = isB ? 4 + dd : dd;
        bool valid = (!isB) || (dd < 2);
        relT[i] = valid ? rel[(g * HD + d) * KW + t] : 0.f;
    }
    for (int i = tid; i < OF * MC; i += 256) {
        int o = i / MC, c = i - o * MC;
        WoT[c * OF + o] = Wp[i];
    }
    if (tid < OF) boS[tid] = bp[tid];
    if (tid < MC) { lngS[tid] = lng[tid]; lnbS[tid] = lnb[tid]; }
    __syncthreads();

    // ---- per-(row-pair, group) attention ----
    {
        const int pair = tid >> 3;
        const int g = tid & 7;
        const int lr0 = pair * 2;
        const int row0g = row0 + lr0;
        const int gb = g * HD;

        float qr0[8], qr1[8];
        {
            const float2* q0 = reinterpret_cast<const float2*>(qkv + (size_t)row0g * N144 + gb);
            const float2* q1 = reinterpret_cast<const float2*>(qkv + (size_t)(row0g + 1) * N144 + gb);
            float2 a = q0[0], b = q0[1], c = q0[2];
            qr0[0]=a.x; qr0[1]=a.y; qr0[2]=b.x; qr0[3]=b.y; qr0[4]=c.x; qr0[5]=c.y;
            qr0[6]=0.f; qr0[7]=0.f;
            a = q1[0]; b = q1[1]; c = q1[2];
            qr1[0]=a.x; qr1[1]=a.y; qr1[2]=b.x; qr1[3]=b.y; qr1[4]=c.x; qr1[5]=c.y;
            qr1[6]=0.f; qr1[7]=0.f;
        }

        float en0[KW], en1[KW];
#pragma unroll
        for (int t = 0; t < KW; t++) {
            float4 ra = *reinterpret_cast<const float4*>(relT + t * RELP8 + g * 4);
            float4 rb = *reinterpret_cast<const float4*>(relT + t * RELP8 + 32 + g * 4);
            en0[t] = dot8(qr0, ra, rb);
            en1[t] = dot8(qr1, ra, rb);
        }
#pragma unroll
        for (int j = 0; j < 32; j++) {
            const float* kr = kv8 + (lr0 + j) * KV8P;
            float4 ka = *reinterpret_cast<const float4*>(kr + g * 4);
            float4 kb = *reinterpret_cast<const float4*>(kr + 32 + g * 4);
            if (j < 31) en0[j] += dot8(qr0, ka, kb);
            if (j > 0)  en1[j - 1] += dot8(qr1, ka, kb);
        }

        float mx0 = en0[0], mx1 = en1[0];
#pragma unroll
        for (int t = 1; t < KW; t++) { mx0 = fmaxf(mx0, en0[t]); mx1 = fmaxf(mx1, en1[t]); }
        float s0 = 0.f, s1 = 0.f;
#pragma unroll
        for (int t = 0; t < KW; t++) {
            en0[t] = __expf(en0[t] - mx0); s0 += en0[t];
            en1[t] = __expf(en1[t] - mx1); s1 += en1[t];
        }
        float i0 = 1.f / s0, i1 = 1.f / s1;
#pragma unroll
        for (int t = 0; t < KW; t++) { en0[t] *= i0; en1[t] *= i1; }

        // attention-weighted V FIRST (kv still needed), then kv region is free
        float xv0[8] = {0,0,0,0,0,0,0,0}, xv1[8] = {0,0,0,0,0,0,0,0};
#pragma unroll
        for (int j = 0; j < 32; j++) {
            const float* vr = kv8 + (lr0 + j) * KV8P;
            float4 va = *reinterpret_cast<const float4*>(vr + 64 + g * 4);
            float4 vb = *reinterpret_cast<const float4*>(vr + 96 + g * 4);
            float fv[8] = {va.x, va.y, va.z, va.w, vb.x, vb.y, vb.z, vb.w};
            if (j < 31) {
                float w = en0[j];
#pragma unroll
                for (int d = 0; d < 8; d++) xv0[d] = fmaf(w, fv[d], xv0[d]);
            }
            if (j > 0) {
                float w = en1[j - 1];
#pragma unroll
                for (int d = 0; d < 8; d++) xv1[d] = fmaf(w, fv[d], xv1[d]);
            }
        }

        // FIRST: a_out via smem staging, 2 passes of 32 rows, coalesced float4
        if constexpr (FIRST) {
            float* abuf = sm + OFF_KV;   // reuse kv region: 32*248 = 7936 <= 12032
#pragma unroll
            for (int p = 0; p < 2; p++) {
                __syncthreads();         // kv reads done (p=0) / prior copy done (p=1)
                if ((lr0 >> 5) == p) {
                    int lr = lr0 & 31;
                    float* d0 = abuf + lr * 248 + g * KW;
#pragma unroll
                    for (int t = 0; t < KW; t++) { d0[t] = en0[t]; d0[248 + t] = en1[t]; }
                }
                __syncthreads();
                float4* dst = reinterpret_cast<float4*>(a_out + (size_t)(row0 + 32 * p) * 248);
                const float4* src = reinterpret_cast<const float4*>(abuf);
                for (int i = tid; i < 32 * 248 / 4; i += 256) dst[i] = src[i];
            }
        }

        // layernorm across 8 group-lanes
        float a0 = 0.f, b0 = 0.f, a1 = 0.f, b1 = 0.f;
#pragma unroll
        for (int d = 0; d < 8; d++) {
            a0 += xv0[d]; b0 = fmaf(xv0[d], xv0[d], b0);
            a1 += xv1[d]; b1 = fmaf(xv1[d], xv1[d], b1);
        }
#pragma unroll
        for (int m = 1; m < 8; m <<= 1) {
            a0 += __shfl_xor_sync(0xffffffffu, a0, m);
            b0 += __shfl_xor_sync(0xffffffffu, b0, m);
            a1 += __shfl_xor_sync(0xffffffffu, a1, m);
            b1 += __shfl_xor_sync(0xffffffffu, b1, m);
        }
        float mu0 = a0 * (1.f / MC), mu1 = a1 * (1.f / MC);
        float r0 = rsqrtf(b0 * (1.f / MC) - mu0 * mu0 + 1e-5f);
        float r1 = rsqrtf(b1 * (1.f / MC) - mu1 * mu1 + 1e-5f);
#pragma unroll
        for (int d = 0; d < HD; d++) {
            float v0 = (xv0[d] - mu0) * r0 * lngS[gb + d] + lnbS[gb + d];
            float v1 = (xv1[d] - mu1) * r1 * lngS[gb + d] + lnbS[gb + d];
            xs[lr0 * XSP + gb + d] = v0;
            xs[(lr0 + 1) * XSP + gb + d] = v1;
        }
    }
    __syncthreads();   // xs complete; kv region free for sigbuf

    // ---- projection + sigmoid into smem buffer [64][88] ----
    float* sigbuf = sm + OFF_KV;   // 64*88 = 5632 <= 12032
    if (tid < 176) {
        const int rq = tid / 11;
        const int o8 = tid - rq * 11;
        float acc[4][8];
#pragma unroll
        for (int j = 0; j < 8; j++) {
            float b = boS[o8 * 8 + j];
#pragma unroll
            for (int r = 0; r < 4; r++) acc[r][j] = b;
        }
#pragma unroll
        for (int c = 0; c < MC; c++) {
            float4 w0 = *reinterpret_cast<const float4*>(&WoT[c * OF + o8 * 8]);
            float4 w1 = *reinterpret_cast<const float4*>(&WoT[c * OF + o8 * 8 + 4]);
            float wv[8] = {w0.x, w0.y, w0.z, w0.w, w1.x, w1.y, w1.z, w1.w};
#pragma unroll
            for (int r = 0; r < 4; r++) {
                float a = xs[(rq * 4 + r) * XSP + c];
#pragma unroll
                for (int j = 0; j < 8; j++)
                    acc[r][j] = fmaf(a, wv[j], acc[r][j]);
            }
        }
#pragma unroll
        for (int r = 0; r < 4; r++) {
            float* srow = sigbuf + (rq * 4 + r) * OF + o8 * 8;
#pragma unroll
            for (int j = 0; j < 8; j++)
                srow[j] = 1.f / (1.f + __expf(-acc[r][j]));
        }
    }
    __syncthreads();

    // ---- coalesced output phase ----
    {
        float4* dst = reinterpret_cast<float4*>(pred_out + (size_t)row0 * OF);
        const float4* src = reinterpret_cast<const float4*>(sigbuf);
        for (int i = tid; i < RPB * OF / 4; i += 256) dst[i] = src[i];
    }
    if constexpr (FIRST) {
        float4* dst = reinterpret_cast<float4*>(g_x2 + (size_t)row0 * 136);
        for (int i = tid; i < RPB * 34; i += 256) {   // 136 floats = 34 float4/row
            int r = i / 34, c4 = i - r * 34;
            float4 v;
            if (c4 < 22)
                v = *reinterpret_cast<const float4*>(sigbuf + r * OF + c4 * 4);
            else
                v = *reinterpret_cast<const float4*>(xs + r * XSP + (c4 - 22) * 4);
            dst[i] = v;
        }
    }
}

// ---------------- launch ----------------
extern "C" void kernel_launch(void* const* d_in, const int* in_sizes, int n_in,
                              void* d_out, int out_size)
{
    const float* spec = (const float*)d_in[0];
    const float* Wq1  = (const float*)d_in[1];
    const float* Wk1  = (const float*)d_in[2];
    const float* Wv1  = (const float*)d_in[3];
    const float* rel1 = (const float*)d_in[4];
    const float* ln1g = (const float*)d_in[5];
    const float* ln1b = (const float*)d_in[6];
    const float* Wo   = (const float*)d_in[7];
    const float* bo   = (const float*)d_in[8];
    const float* Wq2  = (const float*)d_in[9];
    const float* Wk2  = (const float*)d_in[10];
    const float* Wv2  = (const float*)d_in[11];
    const float* rel2 = (const float*)d_in[12];
    const float* ln2g = (const float*)d_in[13];
    const float* ln2b = (const float*)d_in[14];
    const float* Wf   = (const float*)d_in[15];
    const float* bf   = (const float*)d_in[16];

    float* out = (float*)d_out;
    float* frame = out;
    float* onset = out + (size_t)BS * OF;
    float* aout  = out + (size_t)2 * BS * OF;

    void* p_qkv1; cudaGetSymbolAddress(&p_qkv1, g_qkv1);
    void* p_x2;   cudaGetSymbolAddress(&p_x2, g_x2);
    void* p_qkv2; cudaGetSymbolAddress(&p_qkv2, g_qkv2);

    cudaFuncSetAttribute(gemm_qkv_mma<229, 5>,
        cudaFuncAttributeMaxDynamicSharedMemorySize, GEMM_SMEM);
    cudaFuncSetAttribute(gemm_qkv_mma<136, 3>,
        cudaFuncAttributeMaxDynamicSharedMemorySize, GEMM_SMEM);
    cudaFuncSetAttribute(attn_block<true>,
        cudaFuncAttributeMaxDynamicSharedMemorySize, SMEM_BYTES);
    cudaFuncSetAttribute(attn_block<false>,
        cudaFuncAttributeMaxDynamicSharedMemorySize, SMEM_BYTES);

    gemm_qkv_mma<229, 5><<<BS / 128, 256, GEMM_SMEM>>>(spec, Wq1, Wk1, Wv1,
                                                       (float*)p_qkv1);
    attn_block<true><<<BS / RPB, 256, SMEM_BYTES>>>(
        rel1, ln1g, ln1b, Wo, bo, onset, aout);
    gemm_qkv_mma<136, 3><<<BS / 128, 256, GEMM_SMEM>>>((const float*)p_x2,
                                                       Wq2, Wk2, Wv2,
                                                       (float*)p_qkv2);
    attn_block<false><<<BS / RPB, 256, SMEM_BYTES>>>(
        rel2, ln2g, ln2b, Wf, bf, frame, nullptr);
}